// round 8
// baseline (speedup 1.0000x reference)
#include <cuda_runtime.h>

// RoI bilinear pooling:
//   feat: (1, H=200, W=200, C=1024) fp32
//   rois: (N=300, 4) int32  [x0, y0, w, h]
//   out : (N, 7, 7, C) fp32
//
// R8: cp.async software pipeline, barrier-free.
// Thread c consumes exactly bytes [c*16, c*16+16) of each 4KB pixel row, and
// thread c issues the cp.async for those same bytes -> no cross-thread
// dependency, no __syncthreads. Per-thread commit_group/wait_group gives a
// decoupled 2-stage pipeline: in-flight data lives in smem, not registers,
// so MLP depth no longer fights occupancy (the R2/R7 catch-22).

#define POOL  7
#define FH    200
#define FW    200
#define FC    1024
#define VEC   (FC / 4)     // 256 float4 lanes per pixel row
#define NCELL (POOL * POOL)
#define CPC   15           // cells per CTA

__device__ __forceinline__ unsigned smem_u32(const void* p) {
    return (unsigned)__cvta_generic_to_shared(p);
}
__device__ __forceinline__ void cp16(unsigned dst, const void* src) {
    asm volatile("cp.async.cg.shared.global [%0], [%1], 16;\n"
                 :: "r"(dst), "l"(src) : "memory");
}
__device__ __forceinline__ void cp_commit() {
    asm volatile("cp.async.commit_group;\n" ::: "memory");
}
template<int N> __device__ __forceinline__ void cp_wait() {
    asm volatile("cp.async.wait_group %0;\n" :: "n"(N) : "memory");
}

__device__ __forceinline__ int clampi(int v, int lo, int hi) {
    return min(max(v, lo), hi);
}

// Issue the 4 row-chunks (16B each) for global cell g into stage s.
__device__ __forceinline__ void issue_cell(int g, int total,
                                           const float* __restrict__ feat,
                                           const int* __restrict__ rois,
                                           float4 (*buf)[4][VEC], int s, int c)
{
    if (g >= total) return;
    const int n    = g / NCELL;
    const int cell = g - n * NCELL;
    const int py   = cell / POOL;
    const int px   = cell - py * POOL;

    const int4 r = __ldg((const int4*)rois + n);   // x0, y0, w, h

    const float ry  = (float)py * ((float)r.w / (float)POOL);
    const float rx  = (float)px * ((float)r.z / (float)POOL);
    const int   ylo = (int)floorf(ry);
    const int   xlo = (int)floorf(rx);
    const int   yhi = min(ylo + 1, r.w - 1);
    const int   xhi = min(xlo + 1, r.z - 1);

    const int iy0 = clampi(r.y + ylo, 0, FH - 1);
    const int iy1 = clampi(r.y + yhi, 0, FH - 1);
    const int ix0 = clampi(r.x + xlo, 0, FW - 1);
    const int ix1 = clampi(r.x + xhi, 0, FW - 1);

    cp16(smem_u32(&buf[s][0][c]), (const float4*)(feat + ((size_t)iy0 * FW + ix0) * FC) + c);
    cp16(smem_u32(&buf[s][1][c]), (const float4*)(feat + ((size_t)iy0 * FW + ix1) * FC) + c);
    cp16(smem_u32(&buf[s][2][c]), (const float4*)(feat + ((size_t)iy1 * FW + ix0) * FC) + c);
    cp16(smem_u32(&buf[s][3][c]), (const float4*)(feat + ((size_t)iy1 * FW + ix1) * FC) + c);
}

// Consume stage s for global cell g: weights recomputed from rois (L1-hot).
__device__ __forceinline__ void consume_cell(int g, int total,
                                             const int* __restrict__ rois,
                                             float* __restrict__ out,
                                             float4 (*buf)[4][VEC], int s, int c)
{
    if (g >= total) return;
    const int n    = g / NCELL;
    const int cell = g - n * NCELL;
    const int py   = cell / POOL;
    const int px   = cell - py * POOL;

    const int4 r = __ldg((const int4*)rois + n);

    const float ry  = (float)py * ((float)r.w / (float)POOL);
    const float rx  = (float)px * ((float)r.z / (float)POOL);
    const float fy  = ry - floorf(ry);
    const float fx  = rx - floorf(rx);
    const float wx1 = fx, wx0 = 1.0f - fx;
    const float wy1 = fy, wy0 = 1.0f - fy;

    const float4 a = buf[s][0][c];
    const float4 b = buf[s][1][c];
    const float4 gg = buf[s][2][c];
    const float4 d = buf[s][3][c];

    float4 o;
    o.x = (a.x * wx0 + b.x * wx1) * wy0 + (gg.x * wx0 + d.x * wx1) * wy1;
    o.y = (a.y * wx0 + b.y * wx1) * wy0 + (gg.y * wx0 + d.y * wx1) * wy1;
    o.z = (a.z * wx0 + b.z * wx1) * wy0 + (gg.z * wx0 + d.z * wx1) * wy1;
    o.w = (a.w * wx0 + b.w * wx1) * wy0 + (gg.w * wx0 + d.w * wx1) * wy1;

    __stcs((float4*)out + (size_t)g * VEC + c, o);
}

__global__ __launch_bounds__(VEC, 6)
void roi_pool_pipe(const float* __restrict__ feat,
                   const int*   __restrict__ rois,
                   float*       __restrict__ out,
                   int total)
{
    __shared__ float4 buf[2][4][VEC];    // 2 stages x 4 rows x 4KB = 32KB
    const int c  = threadIdx.x;
    const int g0 = blockIdx.x * CPC;
    const int M  = min(CPC, total - g0);   // grid sized so M >= 1

    // prologue: stage 0
    issue_cell(g0, total, feat, rois, buf, 0, c);
    cp_commit();

    for (int i = 0; i < M - 1; i++) {
        issue_cell(g0 + i + 1, total, feat, rois, buf, (i + 1) & 1, c);
        cp_commit();
        cp_wait<1>();                      // stage i landed; i+1 still flying
        consume_cell(g0 + i, total, rois, out, buf, i & 1, c);
    }
    cp_wait<0>();
    consume_cell(g0 + M - 1, total, rois, out, buf, (M - 1) & 1, c);
}

extern "C" void kernel_launch(void* const* d_in, const int* in_sizes, int n_in,
                              void* d_out, int out_size)
{
    const float* feat = (const float*)d_in[0];   // (1,200,200,1024) fp32
    const int*   rois = (const int*)d_in[1];     // (N,4) int32
    const int N = in_sizes[1] / 4;
    const int total = N * NCELL;                 // 14700
    const int grid  = (total + CPC - 1) / CPC;   // 980

    roi_pool_pipe<<<grid, VEC>>>(feat, rois, (float*)d_out, total);
}

// round 9
// speedup vs baseline: 1.0597x; 1.0597x over previous
#include <cuda_runtime.h>
#include <cstdint>

// RoI bilinear pooling:
//   feat: (1, H=200, W=200, C=1024) fp32
//   rois: (N=300, 4) int32  [x0, y0, w, h]
//   out : (N, 7, 7, C) fp32
//
// R9: bulk-async gather. One CTA per (roi, cell). A single thread issues
// 4x cp.async.bulk (whole 4KB pixel rows) -> smem with one mbarrier; the
// 256 threads then consume from smem and stream-store the result.
// Rationale: LDG-based versions plateau at ~4.6TB/s because the per-SM
// outstanding-miss tracking on the L1tex path saturates; the bulk engine
// tracks transfers itself, so 8 CTAs/SM keep 128KB truly in flight, and
// per-CTA issue count drops from ~1030 LDG/STG to 4 bulk ops + stores.

#define POOL  7
#define FH    200
#define FW    200
#define FC    1024
#define VEC   (FC / 4)     // 256 float4 per pixel row
#define NCELL (POOL * POOL)
#define ROW_BYTES (FC * 4) // 4096

__device__ __forceinline__ unsigned smem_u32(const void* p) {
    return (unsigned)__cvta_generic_to_shared(p);
}

__device__ __forceinline__ void mbar_init(unsigned mbar, unsigned count) {
    asm volatile("mbarrier.init.shared.b64 [%0], %1;" :: "r"(mbar), "r"(count) : "memory");
}
__device__ __forceinline__ void mbar_expect_tx(unsigned mbar, unsigned bytes) {
    asm volatile("mbarrier.arrive.expect_tx.shared.b64 _, [%0], %1;"
                 :: "r"(mbar), "r"(bytes) : "memory");
}
__device__ __forceinline__ void bulk_g2s(unsigned dst, const void* src,
                                         unsigned bytes, unsigned mbar) {
    asm volatile("cp.async.bulk.shared::cta.global.mbarrier::complete_tx::bytes "
                 "[%0], [%1], %2, [%3];"
                 :: "r"(dst), "l"(src), "r"(bytes), "r"(mbar) : "memory");
}
__device__ __forceinline__ void mbar_wait_parity0(unsigned mbar) {
    asm volatile(
        "{\n\t"
        ".reg .pred P1;\n\t"
        "WAIT_LOOP_%=:\n\t"
        "mbarrier.try_wait.parity.shared.b64 P1, [%0], 0, 0x989680;\n\t"
        "@P1 bra.uni WAIT_DONE_%=;\n\t"
        "bra.uni WAIT_LOOP_%=;\n\t"
        "WAIT_DONE_%=:\n\t"
        "}"
        :: "r"(mbar) : "memory");
}

__device__ __forceinline__ int clampi(int v, int lo, int hi) {
    return min(max(v, lo), hi);
}

__global__ __launch_bounds__(VEC, 8)
void roi_pool_bulk(const float* __restrict__ feat,
                   const int*   __restrict__ rois,
                   float*       __restrict__ out)
{
    __shared__ alignas(128) float4 buf[4][VEC];   // 4 rows x 4KB = 16KB
    __shared__ alignas(8)  uint64_t mbar_storage;

    const int cell = blockIdx.x;        // 0..48
    const int n    = blockIdx.y;        // roi index
    const int py   = cell / POOL;
    const int px   = cell - py * POOL;
    const int tid  = threadIdx.x;

    const int4 r = __ldg((const int4*)rois + n);  // x0, y0, w, h
    const int x0 = r.x, y0 = r.y, w = r.z, h = r.w;

    const float ry  = (float)py * ((float)h / (float)POOL);
    const float rx  = (float)px * ((float)w / (float)POOL);
    const int   ylo = (int)floorf(ry);
    const int   xlo = (int)floorf(rx);
    const float fy  = ry - (float)ylo;
    const float fx  = rx - (float)xlo;
    const int   yhi = min(ylo + 1, h - 1);
    const int   xhi = min(xlo + 1, w - 1);

    const int iy0 = clampi(y0 + ylo, 0, FH - 1);
    const int iy1 = clampi(y0 + yhi, 0, FH - 1);
    const int ix0 = clampi(x0 + xlo, 0, FW - 1);
    const int ix1 = clampi(x0 + xhi, 0, FW - 1);

    const unsigned mbar = smem_u32(&mbar_storage);

    if (tid == 0) {
        mbar_init(mbar, 1);
        // make init visible to the async proxy before the bulk ops use it
        asm volatile("fence.proxy.async.shared::cta;" ::: "memory");
        mbar_expect_tx(mbar, 4 * ROW_BYTES);
        bulk_g2s(smem_u32(&buf[0][0]), feat + ((size_t)iy0 * FW + ix0) * FC, ROW_BYTES, mbar);
        bulk_g2s(smem_u32(&buf[1][0]), feat + ((size_t)iy0 * FW + ix1) * FC, ROW_BYTES, mbar);
        bulk_g2s(smem_u32(&buf[2][0]), feat + ((size_t)iy1 * FW + ix0) * FC, ROW_BYTES, mbar);
        bulk_g2s(smem_u32(&buf[3][0]), feat + ((size_t)iy1 * FW + ix1) * FC, ROW_BYTES, mbar);
    }
    __syncthreads();          // all threads see initialized mbar before waiting
    mbar_wait_parity0(mbar);  // data landed in smem

    const float wx1 = fx, wx0 = 1.0f - fx;
    const float wy1 = fy, wy0 = 1.0f - fy;

    const float4 a = buf[0][tid];
    const float4 b = buf[1][tid];
    const float4 g = buf[2][tid];
    const float4 d = buf[3][tid];

    float4 o;
    o.x = (a.x * wx0 + b.x * wx1) * wy0 + (g.x * wx0 + d.x * wx1) * wy1;
    o.y = (a.y * wx0 + b.y * wx1) * wy0 + (g.y * wx0 + d.y * wx1) * wy1;
    o.z = (a.z * wx0 + b.z * wx1) * wy0 + (g.z * wx0 + d.z * wx1) * wy1;
    o.w = (a.w * wx0 + b.w * wx1) * wy0 + (g.w * wx0 + d.w * wx1) * wy1;

    __stcs((float4*)out + ((size_t)n * NCELL + cell) * VEC + tid, o);
}

extern "C" void kernel_launch(void* const* d_in, const int* in_sizes, int n_in,
                              void* d_out, int out_size)
{
    const float* feat = (const float*)d_in[0];   // (1,200,200,1024) fp32
    const int*   rois = (const int*)d_in[1];     // (N,4) int32
    const int N = in_sizes[1] / 4;

    dim3 grid(NCELL, N);
    roi_pool_bulk<<<grid, VEC>>>(feat, rois, (float*)d_out);
}

// round 10
// speedup vs baseline: 1.1703x; 1.1043x over previous
#include <cuda_runtime.h>

// RoI bilinear pooling:
//   feat: (1, H=200, W=200, C=1024) fp32
//   rois: (N=300, 4) int32  [x0, y0, w, h]
//   out : (N, 7, 7, C) fp32
//
// R10: champion R2 structure (2 cells/CTA, 7500 CTAs, burst-8 LDG.128,
// occ-8 launch bounds) with micro-opts. Model: kernel is pinned at the
// B300 LTS throughput cap (~6300 B/cyc path-independent): 301 MB of
// L2<->SM traffic (241 MB 4x-redundant reads + 60 MB writes) at ~11.6 TB/s
// = ~26 us. Remaining levers are instruction count (DVFS headroom) and
// store policy only.

#define POOL  7
#define FH    200
#define FW    200
#define FC    1024
#define VEC   (FC / 4)     // 256 float4 per pixel row
#define NCELL (POOL * POOL)
#define NPAIR ((NCELL + 1) / 2)   // 25

__device__ __forceinline__ void cell_setup(int cell, int x0, int y0, int w, int h,
                                           const float* __restrict__ feat,
                                           const float4** p00, const float4** p01,
                                           const float4** p10, const float4** p11,
                                           float* fx, float* fy)
{
    const int py = cell / POOL;
    const int px = cell - py * POOL;

    const float ry = (float)py * ((float)h / (float)POOL);
    const float rx = (float)px * ((float)w / (float)POOL);
    const int ylo = (int)floorf(ry);
    const int xlo = (int)floorf(rx);
    *fy = ry - (float)ylo;
    *fx = rx - (float)xlo;
    const int yhi = min(ylo + 1, h - 1);
    const int xhi = min(xlo + 1, w - 1);

    const int iy0 = min(max(y0 + ylo, 0), FH - 1);
    const int iy1 = min(max(y0 + yhi, 0), FH - 1);
    const int ix0 = min(max(x0 + xlo, 0), FW - 1);
    const int ix1 = min(max(x0 + xhi, 0), FW - 1);

    *p00 = (const float4*)(feat + ((size_t)iy0 * FW + ix0) * FC);
    *p01 = (const float4*)(feat + ((size_t)iy0 * FW + ix1) * FC);
    *p10 = (const float4*)(feat + ((size_t)iy1 * FW + ix0) * FC);
    *p11 = (const float4*)(feat + ((size_t)iy1 * FW + ix1) * FC);
}

// bilinear via lerp form: 6 ops/component, short dependency chain
__device__ __forceinline__ float4 bilerp(float4 a, float4 b, float4 g, float4 d,
                                         float fx, float fy)
{
    float4 t, u, o;
    t.x = fmaf(fx, b.x - a.x, a.x);
    t.y = fmaf(fx, b.y - a.y, a.y);
    t.z = fmaf(fx, b.z - a.z, a.z);
    t.w = fmaf(fx, b.w - a.w, a.w);
    u.x = fmaf(fx, d.x - g.x, g.x);
    u.y = fmaf(fx, d.y - g.y, g.y);
    u.z = fmaf(fx, d.z - g.z, g.z);
    u.w = fmaf(fx, d.w - g.w, g.w);
    o.x = fmaf(fy, u.x - t.x, t.x);
    o.y = fmaf(fy, u.y - t.y, t.y);
    o.z = fmaf(fy, u.z - t.z, t.z);
    o.w = fmaf(fy, u.w - t.w, t.w);
    return o;
}

__global__ __launch_bounds__(VEC, 8)
void roi_pool_kernel(const float* __restrict__ feat,
                     const int*   __restrict__ rois,
                     float*       __restrict__ out)
{
    const int pair = blockIdx.x;            // 0..24
    const int n    = blockIdx.y;            // roi index
    const int cellA = pair * 2;
    const bool hasB = (cellA + 1) < NCELL;
    const int cellB = hasB ? (cellA + 1) : cellA;

    const int4 r = __ldg(((const int4*)rois) + n);
    const int x0 = r.x, y0 = r.y, w = r.z, h = r.w;

    const float4 *a00, *a01, *a10, *a11;
    const float4 *b00, *b01, *b10, *b11;
    float afx, afy, bfx, bfy;

    cell_setup(cellA, x0, y0, w, h, feat, &a00, &a01, &a10, &a11, &afx, &afy);
    cell_setup(cellB, x0, y0, w, h, feat, &b00, &b01, &b10, &b11, &bfx, &bfy);

    const int c = threadIdx.x;              // 0..255 float4 lanes

    // Burst-issue all 8 loads before any use.
    const float4 va = __ldg(a00 + c);
    const float4 vb = __ldg(a01 + c);
    const float4 vg = __ldg(a10 + c);
    const float4 vd = __ldg(a11 + c);
    const float4 ua = __ldg(b00 + c);
    const float4 ub = __ldg(b01 + c);
    const float4 ug = __ldg(b10 + c);
    const float4 ud = __ldg(b11 + c);

    float4* outv = (float4*)out;
    const size_t base = (size_t)n * NCELL;

    // Streaming stores: output is write-once, keep L2 for feat.
    __stcs(outv + (base + cellA) * VEC + c, bilerp(va, vb, vg, vd, afx, afy));

    if (hasB) {
        __stcs(outv + (base + cellB) * VEC + c, bilerp(ua, ub, ug, ud, bfx, bfy));
    }
}

extern "C" void kernel_launch(void* const* d_in, const int* in_sizes, int n_in,
                              void* d_out, int out_size)
{
    const float* feat = (const float*)d_in[0];   // (1,200,200,1024) fp32
    const int*   rois = (const int*)d_in[1];     // (N,4) int32
    const int N = in_sizes[1] / 4;

    dim3 grid(NPAIR, N);
    roi_pool_kernel<<<grid, VEC>>>(feat, rois, (float*)d_out);
}